// round 9
// baseline (speedup 1.0000x reference)
#include <cuda_runtime.h>
#include <cuda_bf16.h>
#include <mma.h>
#include <math.h>
#include <stdint.h>

using namespace nvcuda;

#define N_   64
#define C_   512
#define P_   1024
#define KA   65
#define KC   64
#define EPSF 1e-12f
#define PSPL 2       // p-split for gemm2

// ---------------- scratch (device globals: allocation-free) ----------------
__device__ float         g_inv[N_ * P_];
__device__ __nv_bfloat16 g_a[N_ * KC * P_];          // softmax weights, bf16
__device__ float         g_aggp[PSPL * N_ * KC * C_]; // partial aggregation
__device__ float         g_nsq[N_];

#define LDA1 72      // smem leading dim for bf16 tiles (144B rows)
#define LDO1 84      // smem leading dim for f32 out tile (336B rows)

// ============ GEMM1: logits (tensor cores) + fused L2 norm + softmax ============
// Per CTA: sample n, 128-pixel tile.  D[p=128, k=80pad] = bf16(x^T) * bf16(w)^T,
// K = 512 channels in 8 chunks of 64.  Software-pipelined register prefetch.
__global__ void __launch_bounds__(128) k_gemm1(const float* __restrict__ x,
                                               const float* __restrict__ w,
                                               const float* __restrict__ b) {
    // union: { ws[80][72]bf16 | xa[128][72]bf16 } vs outp[128][84]f32 vs ta[64][128]bf16
    __shared__ __align__(16) char smbuf[43008];
    __shared__ float bs[KA];
    __nv_bfloat16* ws = reinterpret_cast<__nv_bfloat16*>(smbuf);
    __nv_bfloat16* xa = reinterpret_cast<__nv_bfloat16*>(smbuf + 11520);
    float* outp = reinterpret_cast<float*>(smbuf);

    int n = blockIdx.x;
    int pblk = blockIdx.y * 128;
    int tid = threadIdx.x;
    int wid = tid >> 5;
    int lane = tid & 31;
    if (tid < KA) bs[tid] = b[tid];

    wmma::fragment<wmma::accumulator, 16, 16, 16, float> acc[2][5];
#pragma unroll
    for (int i = 0; i < 2; i++)
#pragma unroll
        for (int j = 0; j < 5; j++) wmma::fill_fragment(acc[i][j], 0.f);

    float sumsq = 0.f;
    const float* xp = x + (size_t)n * C_ * P_ + pblk + tid;
    uint32_t xr[32];   // packed bf16x2: 64 channels of this thread's pixel
    uint32_t wr[20];   // packed bf16x2: this thread's share of the w chunk

#define G1_LOAD(c0_)                                                           \
    do {                                                                       \
        _Pragma("unroll")                                                      \
        for (int j = 0; j < 32; j++) {                                         \
            float v0 = xp[(size_t)((c0_) + 2 * j) * P_];                       \
            float v1 = xp[(size_t)((c0_) + 2 * j + 1) * P_];                   \
            sumsq = fmaf(v0, v0, sumsq);                                       \
            sumsq = fmaf(v1, v1, sumsq);                                       \
            __nv_bfloat162 h = __floats2bfloat162_rn(v0, v1);                  \
            xr[j] = *reinterpret_cast<uint32_t*>(&h);                          \
        }                                                                      \
        _Pragma("unroll")                                                      \
        for (int i = 0; i < 20; i++) {                                         \
            int r = wid + 4 * i;                                               \
            float f0 = 0.f, f1 = 0.f;                                          \
            if (r < KA) {                                                      \
                float2 v = *reinterpret_cast<const float2*>(                   \
                    w + r * C_ + (c0_) + 2 * lane);                            \
                f0 = v.x; f1 = v.y;                                            \
            }                                                                  \
            __nv_bfloat162 h = __floats2bfloat162_rn(f0, f1);                  \
            wr[i] = *reinterpret_cast<uint32_t*>(&h);                          \
        }                                                                      \
    } while (0)

    G1_LOAD(0);

    for (int ch = 0; ch < 8; ch++) {
        __syncthreads();   // previous mma done reading smem
#pragma unroll
        for (int j = 0; j < 32; j++)
            *reinterpret_cast<uint32_t*>(&xa[tid * LDA1 + 2 * j]) = xr[j];
#pragma unroll
        for (int i = 0; i < 20; i++)
            *reinterpret_cast<uint32_t*>(&ws[(wid + 4 * i) * LDA1 + 2 * lane]) = wr[i];
        __syncthreads();

        if (ch < 7) G1_LOAD((ch + 1) * 64);   // LDGs in flight during mma below

#pragma unroll
        for (int ks = 0; ks < 4; ks++) {
            wmma::fragment<wmma::matrix_a, 16, 16, 16, __nv_bfloat16, wmma::row_major> af[2];
#pragma unroll
            for (int i = 0; i < 2; i++)
                wmma::load_matrix_sync(af[i], xa + (32 * wid + 16 * i) * LDA1 + 16 * ks, LDA1);
#pragma unroll
            for (int j = 0; j < 5; j++) {
                wmma::fragment<wmma::matrix_b, 16, 16, 16, __nv_bfloat16, wmma::col_major> bf;
                wmma::load_matrix_sync(bf, ws + (16 * j) * LDA1 + 16 * ks, LDA1);
#pragma unroll
                for (int i = 0; i < 2; i++) wmma::mma_sync(acc[i][j], af[i], bf, acc[i][j]);
            }
        }
    }
#undef G1_LOAD

    __syncthreads();   // smem reuse: bf16 tiles -> f32 out tile
#pragma unroll
    for (int i = 0; i < 2; i++)
#pragma unroll
        for (int j = 0; j < 5; j++)
            wmma::store_matrix_sync(outp + (32 * wid + 16 * i) * LDO1 + 16 * j,
                                    acc[i][j], LDO1, wmma::mem_row_major);
    __syncthreads();

    // epilogue: thread = pixel. logits = D*inv + b ; softmax over 65
    float inv = 1.f / fmaxf(sqrtf(sumsq), EPSF);
    g_inv[n * P_ + pblk + tid] = inv;

    float l[KA];
    const float* orow = outp + tid * LDO1;
#pragma unroll
    for (int k = 0; k < KA; k++) l[k] = fmaf(orow[k], inv, bs[k]);
    float m = l[0];
#pragma unroll
    for (int k = 1; k < KA; k++) m = fmaxf(m, l[k]);
    float s = 0.f;
#pragma unroll
    for (int k = 0; k < KA; k++) { float e = __expf(l[k] - m); l[k] = e; s += e; }
    float rs = 1.f / s;

    // transpose a through smem -> fully coalesced global stores
    __syncthreads();   // done reading outp
    __nv_bfloat16* ta = reinterpret_cast<__nv_bfloat16*>(smbuf);  // [64][128]
#pragma unroll
    for (int k = 0; k < KC; k++) ta[k * 128 + tid] = __float2bfloat16(l[k] * rs);
    __syncthreads();
    const uint32_t* taw = reinterpret_cast<const uint32_t*>(ta);  // [64][64] words
    uint32_t* gaw = reinterpret_cast<uint32_t*>(g_a);
    size_t gbase = (size_t)n * KC * (P_ / 2) + (pblk >> 1);
#pragma unroll
    for (int it = 0; it < 32; it++) {
        int idx = it * 128 + tid;
        int k = idx >> 6, wd = idx & 63;
        gaw[gbase + (size_t)k * (P_ / 2) + wd] = taw[idx];
    }
}

// ============ GEMM2: aggregation (tensor cores), pipelined, p-split x2 ============
// Per CTA: sample n, 128-channel tile, half of the p range.
// D[k=64, c=128] = sum_{p in half} a[k,p] * (x*inv)[c,p]^T, 8 chunks of 64.
__global__ void __launch_bounds__(128) k_gemm2(const float* __restrict__ x) {
    __shared__ __align__(16) __nv_bfloat16 xs[128 * LDA1];   // [c][p-chunk]

    int n = blockIdx.x;
    int cbase = blockIdx.y * 128;
    int z = blockIdx.z;
    int tid = threadIdx.x;
    int wid = tid >> 5;
    int lane = tid & 31;
    if (blockIdx.y == 0 && z == 0 && tid == 0) g_nsq[n] = 0.f;

    wmma::fragment<wmma::accumulator, 16, 16, 16, float> acc[8];
#pragma unroll
    for (int j = 0; j < 8; j++) wmma::fill_fragment(acc[j], 0.f);

    const __nv_bfloat16* abase = g_a + ((size_t)n * KC + 16 * wid) * P_;
    uint32_t xr[32];

#define G2_LOAD(p0_)                                                           \
    do {                                                                       \
        float2 iv = *reinterpret_cast<const float2*>(g_inv + n * P_ + (p0_) + 2 * lane); \
        _Pragma("unroll")                                                      \
        for (int rr = 0; rr < 32; rr++) {                                      \
            int r = wid + 4 * rr;                                              \
            float2 xv = *reinterpret_cast<const float2*>(                      \
                x + ((size_t)n * C_ + cbase + r) * P_ + (p0_) + 2 * lane);     \
            __nv_bfloat162 h = __floats2bfloat162_rn(xv.x * iv.x, xv.y * iv.y);\
            xr[rr] = *reinterpret_cast<uint32_t*>(&h);                         \
        }                                                                      \
    } while (0)

    int pstart = z * (P_ / PSPL);
    G2_LOAD(pstart);

    for (int ch = 0; ch < 8; ch++) {
        __syncthreads();
#pragma unroll
        for (int rr = 0; rr < 32; rr++)
            *reinterpret_cast<uint32_t*>(&xs[(wid + 4 * rr) * LDA1 + 2 * lane]) = xr[rr];
        __syncthreads();

        int p0 = pstart + ch * 64;
        if (ch < 7) G2_LOAD(p0 + 64);   // LDGs in flight during mma below

        wmma::fragment<wmma::matrix_a, 16, 16, 16, __nv_bfloat16, wmma::row_major> af[4];
#pragma unroll
        for (int ks = 0; ks < 4; ks++)
            wmma::load_matrix_sync(af[ks], abase + p0 + 16 * ks, P_);
#pragma unroll
        for (int ks = 0; ks < 4; ks++) {
#pragma unroll
            for (int j = 0; j < 8; j++) {
                wmma::fragment<wmma::matrix_b, 16, 16, 16, __nv_bfloat16, wmma::col_major> bf;
                wmma::load_matrix_sync(bf, xs + (16 * j) * LDA1 + 16 * ks, LDA1);
                wmma::mma_sync(acc[j], af[ks], bf, acc[j]);
            }
        }
    }
#undef G2_LOAD

    float* dbase = g_aggp + (((size_t)z * N_ + n) * KC + 16 * wid) * C_ + cbase;
#pragma unroll
    for (int j = 0; j < 8; j++)
        wmma::store_matrix_sync(dbase + 16 * j, acc[j], C_, wmma::mem_row_major);
}

// ------- partial-sum + centroid subtract + per-row L2 (asum inline from g_a) -------
__global__ void __launch_bounds__(128) k_rownorm(const float* __restrict__ cent,
                                                 float* __restrict__ out) {
    int n = blockIdx.x, k = blockIdx.y;
    int tid = threadIdx.x;
    __shared__ float red[4];
    __shared__ float bcast;

    // asum[n][k] = sum_p a[k][p] : 1024 bf16 = 128 threads x uint4 (8 values)
    const __nv_bfloat16* ap = g_a + ((size_t)n * KC + k) * P_;
    uint4 u = reinterpret_cast<const uint4*>(ap)[tid];
    float asv = 0.f;
    {
        uint32_t parts[4] = {u.x, u.y, u.z, u.w};
#pragma unroll
        for (int i = 0; i < 4; i++) {
            __nv_bfloat162 h = *reinterpret_cast<__nv_bfloat162*>(&parts[i]);
            asv += __low2float(h) + __high2float(h);
        }
    }
#pragma unroll
    for (int o = 16; o; o >>= 1) asv += __shfl_xor_sync(0xFFFFFFFFu, asv, o);
    if ((tid & 31) == 0) red[tid >> 5] = asv;
    __syncthreads();
    if (tid == 0) bcast = red[0] + red[1] + red[2] + red[3];
    __syncthreads();
    float as = bcast;
    __syncthreads();   // protect red/bcast before reuse

    float v[4];
    float s = 0.f;
    size_t base = ((size_t)n * KC + k) * C_;
    const size_t zs = (size_t)N_ * KC * C_;
#pragma unroll
    for (int j = 0; j < 4; j++) {
        int c = tid + j * 128;
        float val = g_aggp[base + c] + g_aggp[zs + base + c] - as * cent[k * C_ + c];
        v[j] = val;
        s = fmaf(val, val, s);
    }
#pragma unroll
    for (int o = 16; o; o >>= 1) s += __shfl_xor_sync(0xFFFFFFFFu, s, o);
    if ((tid & 31) == 0) red[tid >> 5] = s;
    __syncthreads();
    if (tid == 0) bcast = red[0] + red[1] + red[2] + red[3];
    __syncthreads();
    float total = bcast;
    float invn = 1.f / fmaxf(sqrtf(total), EPSF);
#pragma unroll
    for (int j = 0; j < 4; j++) {
        int c = tid + j * 128;
        out[(size_t)n * KC * C_ + (size_t)k * C_ + c] = v[j] * invn;
    }
    if (tid == 0) atomicAdd(&g_nsq[n], total * invn * invn);
}

// ---------------- global L2 normalize ----------------
__global__ void __launch_bounds__(256) k_final(float* __restrict__ out) {
    int n = blockIdx.x;
    float scale = 1.f / fmaxf(sqrtf(g_nsq[n]), EPSF);
    size_t idx = (size_t)n * (KC * C_) + ((size_t)blockIdx.y * 256 + threadIdx.x) * 4;
    float4* o = reinterpret_cast<float4*>(out + idx);
    float4 v = *o;
    v.x *= scale; v.y *= scale; v.z *= scale; v.w *= scale;
    *o = v;
}

// ---------------- launch ----------------
extern "C" void kernel_launch(void* const* d_in, const int* in_sizes, int n_in,
                              void* d_out, int out_size) {
    const float* x    = (const float*)d_in[0];
    const float* w    = (const float*)d_in[1];
    const float* b    = (const float*)d_in[2];
    const float* cent = (const float*)d_in[3];
    float* out = (float*)d_out;

    k_gemm1<<<dim3(N_, 8), 128>>>(x, w, b);
    k_gemm2<<<dim3(N_, 4, PSPL), 128>>>(x);
    k_rownorm<<<dim3(N_, KC), 128>>>(cent, out);
    k_final<<<dim3(N_, 32), 256>>>(out);
}

// round 10
// speedup vs baseline: 1.0781x; 1.0781x over previous
#include <cuda_runtime.h>
#include <cuda_bf16.h>
#include <mma.h>
#include <math.h>
#include <stdint.h>

using namespace nvcuda;

#define N_   64
#define C_   512
#define P_   1024
#define KA   65
#define KC   64
#define EPSF 1e-12f

// ---------------- scratch (device globals: allocation-free) ----------------
__device__ float         g_inv[N_ * P_];
__device__ __nv_bfloat16 g_a[N_ * KC * P_];      // softmax weights, bf16
__device__ float         g_agg[N_ * KC * C_];
__device__ float         g_nsq[N_];

#define LDA1 72      // smem leading dim for bf16 tiles (144B rows)
#define LDO1 84      // smem leading dim for f32 out tile (336B rows)

// ============ GEMM1: logits (tensor cores) + fused L2 norm + softmax ============
// Per CTA: sample n, 128-pixel tile.  D[p=128, k=80pad] = bf16(x^T) * bf16(w)^T,
// K = 512 channels in 8 chunks of 64.  Software-pipelined register prefetch.
__global__ void __launch_bounds__(128) k_gemm1(const float* __restrict__ x,
                                               const float* __restrict__ w,
                                               const float* __restrict__ b) {
    // union: { ws[80][72]bf16 (11520B) | xa[128][72]bf16 (18432B) } vs outp[128][84]f32
    __shared__ __align__(16) char smbuf[43008];
    __shared__ float bs[KA];
    __nv_bfloat16* ws = reinterpret_cast<__nv_bfloat16*>(smbuf);
    __nv_bfloat16* xa = reinterpret_cast<__nv_bfloat16*>(smbuf + 11520);
    float* outp = reinterpret_cast<float*>(smbuf);

    int n = blockIdx.x;
    int pblk = blockIdx.y * 128;
    int tid = threadIdx.x;
    int wid = tid >> 5;
    int lane = tid & 31;
    if (tid < KA) bs[tid] = b[tid];

    wmma::fragment<wmma::accumulator, 16, 16, 16, float> acc[2][5];
#pragma unroll
    for (int i = 0; i < 2; i++)
#pragma unroll
        for (int j = 0; j < 5; j++) wmma::fill_fragment(acc[i][j], 0.f);

    float sumsq = 0.f;
    const float* xp = x + (size_t)n * C_ * P_ + pblk + tid;
    uint32_t xr[32];   // packed bf16x2: 64 channels of this thread's pixel
    uint32_t wr[20];   // packed bf16x2: this thread's share of the w chunk

#define G1_LOAD(c0_)                                                           \
    do {                                                                       \
        _Pragma("unroll")                                                      \
        for (int j = 0; j < 32; j++) {                                         \
            float v0 = xp[(size_t)((c0_) + 2 * j) * P_];                       \
            float v1 = xp[(size_t)((c0_) + 2 * j + 1) * P_];                   \
            sumsq = fmaf(v0, v0, sumsq);                                       \
            sumsq = fmaf(v1, v1, sumsq);                                       \
            __nv_bfloat162 h = __floats2bfloat162_rn(v0, v1);                  \
            xr[j] = *reinterpret_cast<uint32_t*>(&h);                          \
        }                                                                      \
        _Pragma("unroll")                                                      \
        for (int i = 0; i < 20; i++) {                                         \
            int r = wid + 4 * i;                                               \
            float f0 = 0.f, f1 = 0.f;                                          \
            if (r < KA) {                                                      \
                float2 v = *reinterpret_cast<const float2*>(                   \
                    w + r * C_ + (c0_) + 2 * lane);                            \
                f0 = v.x; f1 = v.y;                                            \
            }                                                                  \
            __nv_bfloat162 h = __floats2bfloat162_rn(f0, f1);                  \
            wr[i] = *reinterpret_cast<uint32_t*>(&h);                          \
        }                                                                      \
    } while (0)

    G1_LOAD(0);

    for (int ch = 0; ch < 8; ch++) {
        __syncthreads();   // previous mma done reading smem
#pragma unroll
        for (int j = 0; j < 32; j++)
            *reinterpret_cast<uint32_t*>(&xa[tid * LDA1 + 2 * j]) = xr[j];
#pragma unroll
        for (int i = 0; i < 20; i++)
            *reinterpret_cast<uint32_t*>(&ws[(wid + 4 * i) * LDA1 + 2 * lane]) = wr[i];
        __syncthreads();

        if (ch < 7) G1_LOAD((ch + 1) * 64);   // LDGs in flight during mma below

#pragma unroll
        for (int ks = 0; ks < 4; ks++) {
            wmma::fragment<wmma::matrix_a, 16, 16, 16, __nv_bfloat16, wmma::row_major> af[2];
#pragma unroll
            for (int i = 0; i < 2; i++)
                wmma::load_matrix_sync(af[i], xa + (32 * wid + 16 * i) * LDA1 + 16 * ks, LDA1);
#pragma unroll
            for (int j = 0; j < 5; j++) {
                wmma::fragment<wmma::matrix_b, 16, 16, 16, __nv_bfloat16, wmma::col_major> bf;
                wmma::load_matrix_sync(bf, ws + (16 * j) * LDA1 + 16 * ks, LDA1);
#pragma unroll
                for (int i = 0; i < 2; i++) wmma::mma_sync(acc[i][j], af[i], bf, acc[i][j]);
            }
        }
    }
#undef G1_LOAD

    __syncthreads();   // smem reuse: bf16 tiles -> f32 out tile
#pragma unroll
    for (int i = 0; i < 2; i++)
#pragma unroll
        for (int j = 0; j < 5; j++)
            wmma::store_matrix_sync(outp + (32 * wid + 16 * i) * LDO1 + 16 * j,
                                    acc[i][j], LDO1, wmma::mem_row_major);
    __syncthreads();

    // epilogue: thread = pixel. logits = D*inv + b ; softmax over 65 ; store a (bf16)
    float inv = 1.f / fmaxf(sqrtf(sumsq), EPSF);
    g_inv[n * P_ + pblk + tid] = inv;

    float l[KA];
    const float* orow = outp + tid * LDO1;
#pragma unroll
    for (int k = 0; k < KA; k++) l[k] = fmaf(orow[k], inv, bs[k]);
    float m = l[0];
#pragma unroll
    for (int k = 1; k < KA; k++) m = fmaxf(m, l[k]);
    float s = 0.f;
#pragma unroll
    for (int k = 0; k < KA; k++) { float e = __expf(l[k] - m); l[k] = e; s += e; }
    float rs = 1.f / s;

    __nv_bfloat16* ao = g_a + (size_t)n * KC * P_ + pblk + tid;
#pragma unroll
    for (int k = 0; k < KC; k++) ao[(size_t)k * P_] = __float2bfloat16(l[k] * rs);
}

// ============ GEMM2: aggregation (tensor cores), pipelined, 64-c tiles ============
// Per CTA: sample n, 64-channel tile.  D[k=64, c=64] = a[k,p] * (x*inv)[c,p]^T,
// K = 1024 pixels in 16 chunks of 64.  Warp w owns cluster rows [16w, 16w+16).
// Grid (64, 8) = 512 CTAs; light CTAs (9KB smem, 4 accum frags) for ~3.5 CTAs/SM.
__global__ void __launch_bounds__(128) k_gemm2(const float* __restrict__ x) {
    __shared__ __align__(16) __nv_bfloat16 xs[64 * LDA1];   // [c][p-chunk], 9216B

    int n = blockIdx.x;
    int cbase = blockIdx.y * 64;
    int tid = threadIdx.x;
    int wid = tid >> 5;
    int lane = tid & 31;
    if (blockIdx.y == 0 && tid == 0) g_nsq[n] = 0.f;   // reset before k_rownorm

    wmma::fragment<wmma::accumulator, 16, 16, 16, float> acc[4];
#pragma unroll
    for (int j = 0; j < 4; j++) wmma::fill_fragment(acc[j], 0.f);

    const __nv_bfloat16* abase = g_a + ((size_t)n * KC + 16 * wid) * P_;
    uint32_t xr[16];

#define G2_LOAD(p0_)                                                           \
    do {                                                                       \
        float2 iv = *reinterpret_cast<const float2*>(g_inv + n * P_ + (p0_) + 2 * lane); \
        _Pragma("unroll")                                                      \
        for (int rr = 0; rr < 16; rr++) {                                      \
            int r = wid + 4 * rr;                                              \
            float2 xv = *reinterpret_cast<const float2*>(                      \
                x + ((size_t)n * C_ + cbase + r) * P_ + (p0_) + 2 * lane);     \
            __nv_bfloat162 h = __floats2bfloat162_rn(xv.x * iv.x, xv.y * iv.y);\
            xr[rr] = *reinterpret_cast<uint32_t*>(&h);                         \
        }                                                                      \
    } while (0)

    G2_LOAD(0);

    for (int ch = 0; ch < 16; ch++) {
        __syncthreads();
#pragma unroll
        for (int rr = 0; rr < 16; rr++)
            *reinterpret_cast<uint32_t*>(&xs[(wid + 4 * rr) * LDA1 + 2 * lane]) = xr[rr];
        __syncthreads();

        int p0 = ch * 64;
        if (ch < 15) G2_LOAD(p0 + 64);   // LDGs in flight during mma below

        wmma::fragment<wmma::matrix_a, 16, 16, 16, __nv_bfloat16, wmma::row_major> af[4];
#pragma unroll
        for (int ks = 0; ks < 4; ks++)
            wmma::load_matrix_sync(af[ks], abase + p0 + 16 * ks, P_);
#pragma unroll
        for (int ks = 0; ks < 4; ks++) {
#pragma unroll
            for (int j = 0; j < 4; j++) {
                wmma::fragment<wmma::matrix_b, 16, 16, 16, __nv_bfloat16, wmma::col_major> bf;
                wmma::load_matrix_sync(bf, xs + (16 * j) * LDA1 + 16 * ks, LDA1);
                wmma::mma_sync(acc[j], af[ks], bf, acc[j]);
            }
        }
    }
#undef G2_LOAD

    float* dbase = g_agg + ((size_t)n * KC + 16 * wid) * C_ + cbase;
#pragma unroll
    for (int j = 0; j < 4; j++)
        wmma::store_matrix_sync(dbase + 16 * j, acc[j], C_, wmma::mem_row_major);
}

// ------- centroid subtract + per-row L2 (asum computed inline from g_a) -------
__global__ void __launch_bounds__(128) k_rownorm(const float* __restrict__ cent,
                                                 float* __restrict__ out) {
    int n = blockIdx.x, k = blockIdx.y;
    int tid = threadIdx.x;
    __shared__ float red[4];
    __shared__ float bcast;

    // asum[n][k] = sum_p a[k][p] : 1024 bf16 = 128 threads x uint4 (8 values)
    const __nv_bfloat16* ap = g_a + ((size_t)n * KC + k) * P_;
    uint4 u = reinterpret_cast<const uint4*>(ap)[tid];
    float asv = 0.f;
    {
        uint32_t parts[4] = {u.x, u.y, u.z, u.w};
#pragma unroll
        for (int i = 0; i < 4; i++) {
            __nv_bfloat162 h = *reinterpret_cast<__nv_bfloat162*>(&parts[i]);
            asv += __low2float(h) + __high2float(h);
        }
    }
#pragma unroll
    for (int o = 16; o; o >>= 1) asv += __shfl_xor_sync(0xFFFFFFFFu, asv, o);
    if ((tid & 31) == 0) red[tid >> 5] = asv;
    __syncthreads();
    if (tid == 0) bcast = red[0] + red[1] + red[2] + red[3];
    __syncthreads();
    float as = bcast;
    __syncthreads();   // protect red/bcast before reuse

    float v[4];
    float s = 0.f;
    size_t base = ((size_t)n * KC + k) * C_;
#pragma unroll
    for (int j = 0; j < 4; j++) {
        int c = tid + j * 128;
        float val = g_agg[base + c] - as * cent[k * C_ + c];
        v[j] = val;
        s = fmaf(val, val, s);
    }
#pragma unroll
    for (int o = 16; o; o >>= 1) s += __shfl_xor_sync(0xFFFFFFFFu, s, o);
    if ((tid & 31) == 0) red[tid >> 5] = s;
    __syncthreads();
    if (tid == 0) bcast = red[0] + red[1] + red[2] + red[3];
    __syncthreads();
    float total = bcast;
    float invn = 1.f / fmaxf(sqrtf(total), EPSF);
#pragma unroll
    for (int j = 0; j < 4; j++) {
        int c = tid + j * 128;
        out[(size_t)n * KC * C_ + (size_t)k * C_ + c] = v[j] * invn;
    }
    if (tid == 0) atomicAdd(&g_nsq[n], total * invn * invn);
}

// ---------------- global L2 normalize ----------------
__global__ void __launch_bounds__(256) k_final(float* __restrict__ out) {
    int n = blockIdx.x;
    float scale = 1.f / fmaxf(sqrtf(g_nsq[n]), EPSF);
    size_t idx = (size_t)n * (KC * C_) + ((size_t)blockIdx.y * 256 + threadIdx.x) * 4;
    float4* o = reinterpret_cast<float4*>(out + idx);
    float4 v = *o;
    v.x *= scale; v.y *= scale; v.z *= scale; v.w *= scale;
    *o = v;
}

// ---------------- launch ----------------
extern "C" void kernel_launch(void* const* d_in, const int* in_sizes, int n_in,
                              void* d_out, int out_size) {
    const float* x    = (const float*)d_in[0];
    const float* w    = (const float*)d_in[1];
    const float* b    = (const float*)d_in[2];
    const float* cent = (const float*)d_in[3];
    float* out = (float*)d_out;

    k_gemm1<<<dim3(N_, 8), 128>>>(x, w, b);
    k_gemm2<<<dim3(N_, 8), 128>>>(x);
    k_rownorm<<<dim3(N_, KC), 128>>>(cent, out);
    k_final<<<dim3(N_, 32), 256>>>(out);
}

// round 11
// speedup vs baseline: 1.1318x; 1.0497x over previous
#include <cuda_runtime.h>
#include <cuda_bf16.h>
#include <mma.h>
#include <math.h>
#include <stdint.h>

using namespace nvcuda;

#define N_   64
#define C_   512
#define P_   1024
#define KA   65
#define KC   64
#define EPSF 1e-12f

// ---------------- scratch (device globals: allocation-free) ----------------
__device__ float         g_inv[N_ * P_];
__device__ __nv_bfloat16 g_a[N_ * KC * P_];      // softmax weights, bf16
__device__ float         g_agg[N_ * KC * C_];
__device__ float         g_nsq[N_];

#define LDA1 72      // ws leading dim (k-major w tile), elems
#define LDXS 136     // [c][p] tile leading dim (128 px + 8 pad), elems
#define LDO1 84      // f32 out tile leading dim, elems

__device__ __forceinline__ uint32_t bfpack(float a, float b) {
    __nv_bfloat162 h = __floats2bfloat162_rn(a, b);
    return *reinterpret_cast<uint32_t*>(&h);
}

// ============ GEMM1: logits (tensor cores) + fused L2 norm + softmax ============
// Per CTA: sample n, 128-pixel tile.  D[p=128, k=80pad] = A[p,c] * W[k,c]^T,
// K = 512 channels in 8 chunks of 64.  x staged in native [c][p] layout:
// float4 LDGs along p, conflict-free STS.64, A fragments loaded col_major.
__global__ void __launch_bounds__(128) k_gemm1(const float* __restrict__ x,
                                               const float* __restrict__ w,
                                               const float* __restrict__ b) {
    // union: { ws[80][72]bf16 (11520B) | xa[64][136]bf16 (17408B) } vs outp[128][84]f32
    __shared__ __align__(16) char smbuf[43008];
    __shared__ float bs[KA];
    __shared__ float sq[4][128];                  // per-warp sumsq partials
    __nv_bfloat16* ws = reinterpret_cast<__nv_bfloat16*>(smbuf);
    __nv_bfloat16* xa = reinterpret_cast<__nv_bfloat16*>(smbuf + 11520);
    float* outp = reinterpret_cast<float*>(smbuf);

    int n = blockIdx.x;
    int pblk = blockIdx.y * 128;
    int tid = threadIdx.x;
    int wid = tid >> 5;
    int lane = tid & 31;
    int px4 = 4 * lane;                           // this thread's 4 pixels
    if (tid < KA) bs[tid] = b[tid];

    wmma::fragment<wmma::accumulator, 16, 16, 16, float> acc[2][5];
#pragma unroll
    for (int i = 0; i < 2; i++)
#pragma unroll
        for (int j = 0; j < 5; j++) wmma::fill_fragment(acc[i][j], 0.f);

    float sqa[4] = {0.f, 0.f, 0.f, 0.f};
    const float* xg = x + (size_t)n * C_ * P_ + pblk;
    uint32_t xr[32];   // packed bf16x2: 16 (row, 4px) pieces
    uint32_t wr[20];   // packed bf16x2: w chunk share

#define G1_LOAD(c0_)                                                           \
    do {                                                                       \
        _Pragma("unroll")                                                      \
        for (int i = 0; i < 16; i++) {                                         \
            int c = (c0_) + wid + 4 * i;                                       \
            float4 v = *reinterpret_cast<const float4*>(xg + (size_t)c * P_ + px4); \
            sqa[0] = fmaf(v.x, v.x, sqa[0]);                                   \
            sqa[1] = fmaf(v.y, v.y, sqa[1]);                                   \
            sqa[2] = fmaf(v.z, v.z, sqa[2]);                                   \
            sqa[3] = fmaf(v.w, v.w, sqa[3]);                                   \
            xr[2 * i]     = bfpack(v.x, v.y);                                  \
            xr[2 * i + 1] = bfpack(v.z, v.w);                                  \
        }                                                                      \
        _Pragma("unroll")                                                      \
        for (int i = 0; i < 20; i++) {                                         \
            int r = wid + 4 * i;                                               \
            float f0 = 0.f, f1 = 0.f;                                          \
            if (r < KA) {                                                      \
                float2 v = *reinterpret_cast<const float2*>(                   \
                    w + r * C_ + (c0_) + 2 * lane);                            \
                f0 = v.x; f1 = v.y;                                            \
            }                                                                  \
            wr[i] = bfpack(f0, f1);                                            \
        }                                                                      \
    } while (0)

    G1_LOAD(0);

    for (int ch = 0; ch < 8; ch++) {
        __syncthreads();   // previous mma done reading smem
#pragma unroll
        for (int i = 0; i < 16; i++) {
            int row = wid + 4 * i;    // local channel row
            *reinterpret_cast<uint2*>(&xa[row * LDXS + px4]) =
                make_uint2(xr[2 * i], xr[2 * i + 1]);
        }
#pragma unroll
        for (int i = 0; i < 20; i++)
            *reinterpret_cast<uint32_t*>(&ws[(wid + 4 * i) * LDA1 + 2 * lane]) = wr[i];
        __syncthreads();

        if (ch < 7) G1_LOAD((ch + 1) * 64);   // LDGs in flight during mma below

#pragma unroll
        for (int ks = 0; ks < 4; ks++) {
            // A[p, c] tile is xa[c][p]: col_major, ldm = LDXS
            wmma::fragment<wmma::matrix_a, 16, 16, 16, __nv_bfloat16, wmma::col_major> af[2];
#pragma unroll
            for (int i = 0; i < 2; i++)
                wmma::load_matrix_sync(af[i], xa + (16 * ks) * LDXS + 32 * wid + 16 * i, LDXS);
#pragma unroll
            for (int j = 0; j < 5; j++) {
                wmma::fragment<wmma::matrix_b, 16, 16, 16, __nv_bfloat16, wmma::col_major> bf;
                wmma::load_matrix_sync(bf, ws + (16 * j) * LDA1 + 16 * ks, LDA1);
#pragma unroll
                for (int i = 0; i < 2; i++) wmma::mma_sync(acc[i][j], af[i], bf, acc[i][j]);
            }
        }
    }
#undef G1_LOAD

    // publish sumsq partials (4 pixels per thread, one slot per warp)
#pragma unroll
    for (int j = 0; j < 4; j++) sq[wid][px4 + j] = sqa[j];

    __syncthreads();   // smem reuse: bf16 tiles -> f32 out tile
#pragma unroll
    for (int i = 0; i < 2; i++)
#pragma unroll
        for (int j = 0; j < 5; j++)
            wmma::store_matrix_sync(outp + (32 * wid + 16 * i) * LDO1 + 16 * j,
                                    acc[i][j], LDO1, wmma::mem_row_major);
    __syncthreads();

    // epilogue: thread = pixel. logits = D*inv + b ; softmax over 65 ; store a (bf16)
    float sumsq = sq[0][tid] + sq[1][tid] + sq[2][tid] + sq[3][tid];
    float inv = 1.f / fmaxf(sqrtf(sumsq), EPSF);
    g_inv[n * P_ + pblk + tid] = inv;

    float l[KA];
    const float* orow = outp + tid * LDO1;
#pragma unroll
    for (int k = 0; k < KA; k++) l[k] = fmaf(orow[k], inv, bs[k]);
    float m = l[0];
#pragma unroll
    for (int k = 1; k < KA; k++) m = fmaxf(m, l[k]);
    float s = 0.f;
#pragma unroll
    for (int k = 0; k < KA; k++) { float e = __expf(l[k] - m); l[k] = e; s += e; }
    float rs = 1.f / s;

    __nv_bfloat16* ao = g_a + (size_t)n * KC * P_ + pblk + tid;
#pragma unroll
    for (int k = 0; k < KC; k++) ao[(size_t)k * P_] = __float2bfloat16(l[k] * rs);
}

// ============ GEMM2: aggregation (tensor cores), pipelined, 64-c tiles ============
// Per CTA: sample n, 64-channel tile.  D[k=64, c=64] = a[k,p] * (x*inv)[c,p]^T,
// K = 1024 pixels in 8 chunks of 128.  float4 LDGs, conflict-free STS.64.
__global__ void __launch_bounds__(128) k_gemm2(const float* __restrict__ x) {
    __shared__ __align__(16) __nv_bfloat16 xs[64 * LDXS];   // [c][p-chunk], 17408B

    int n = blockIdx.x;
    int cbase = blockIdx.y * 64;
    int tid = threadIdx.x;
    int wid = tid >> 5;
    int lane = tid & 31;
    int px4 = 4 * lane;
    if (blockIdx.y == 0 && tid == 0) g_nsq[n] = 0.f;   // reset before k_rownorm

    wmma::fragment<wmma::accumulator, 16, 16, 16, float> acc[4];
#pragma unroll
    for (int j = 0; j < 4; j++) wmma::fill_fragment(acc[j], 0.f);

    const __nv_bfloat16* abase = g_a + ((size_t)n * KC + 16 * wid) * P_;
    uint32_t xr[32];

#define G2_LOAD(p0_)                                                           \
    do {                                                                       \
        float4 iv = *reinterpret_cast<const float4*>(g_inv + n * P_ + (p0_) + px4); \
        _Pragma("unroll")                                                      \
        for (int i = 0; i < 16; i++) {                                         \
            int r = wid + 4 * i;                                               \
            float4 xv = *reinterpret_cast<const float4*>(                      \
                x + ((size_t)n * C_ + cbase + r) * P_ + (p0_) + px4);          \
            xr[2 * i]     = bfpack(xv.x * iv.x, xv.y * iv.y);                  \
            xr[2 * i + 1] = bfpack(xv.z * iv.z, xv.w * iv.w);                  \
        }                                                                      \
    } while (0)

    G2_LOAD(0);

    for (int ch = 0; ch < 8; ch++) {
        __syncthreads();
#pragma unroll
        for (int i = 0; i < 16; i++) {
            int row = wid + 4 * i;
            *reinterpret_cast<uint2*>(&xs[row * LDXS + px4]) =
                make_uint2(xr[2 * i], xr[2 * i + 1]);
        }
        __syncthreads();

        int p0 = ch * 128;
        if (ch < 7) G2_LOAD(p0 + 128);   // LDGs in flight during mma below

        wmma::fragment<wmma::matrix_a, 16, 16, 16, __nv_bfloat16, wmma::row_major> af[8];
#pragma unroll
        for (int ks = 0; ks < 8; ks++)
            wmma::load_matrix_sync(af[ks], abase + p0 + 16 * ks, P_);
#pragma unroll
        for (int ks = 0; ks < 8; ks++) {
#pragma unroll
            for (int j = 0; j < 4; j++) {
                // B[p, c] tile is xs[c][p]: col_major, ldm = LDXS
                wmma::fragment<wmma::matrix_b, 16, 16, 16, __nv_bfloat16, wmma::col_major> bf;
                wmma::load_matrix_sync(bf, xs + (16 * j) * LDXS + 16 * ks, LDXS);
                wmma::mma_sync(acc[j], af[ks], bf, acc[j]);
            }
        }
    }
#undef G2_LOAD

    float* dbase = g_agg + ((size_t)n * KC + 16 * wid) * C_ + cbase;
#pragma unroll
    for (int j = 0; j < 4; j++)
        wmma::store_matrix_sync(dbase + 16 * j, acc[j], C_, wmma::mem_row_major);
}

// ------- centroid subtract + per-row L2 (asum computed inline from g_a) -------
__global__ void __launch_bounds__(128) k_rownorm(const float* __restrict__ cent,
                                                 float* __restrict__ out) {
    int n = blockIdx.x, k = blockIdx.y;
    int tid = threadIdx.x;
    __shared__ float red[4];
    __shared__ float bcast;

    // asum[n][k] = sum_p a[k][p] : 1024 bf16 = 128 threads x uint4 (8 values)
    const __nv_bfloat16* ap = g_a + ((size_t)n * KC + k) * P_;
    uint4 u = reinterpret_cast<const uint4*>(ap)[tid];
    float asv = 0.f;
    {
        uint32_t parts[4] = {u.x, u.y, u.z, u.w};
#pragma unroll
        for (int i = 0; i < 4; i++) {
            __nv_bfloat162 h = *reinterpret_cast<__nv_bfloat162*>(&parts[i]);
            asv += __low2float(h) + __high2float(h);
        }
    }
#pragma unroll
    for (int o = 16; o; o >>= 1) asv += __shfl_xor_sync(0xFFFFFFFFu, asv, o);
    if ((tid & 31) == 0) red[tid >> 5] = asv;
    __syncthreads();
    if (tid == 0) bcast = red[0] + red[1] + red[2] + red[3];
    __syncthreads();
    float as = bcast;
    __syncthreads();   // protect red/bcast before reuse

    float v[4];
    float s = 0.f;
    size_t base = ((size_t)n * KC + k) * C_;
#pragma unroll
    for (int j = 0; j < 4; j++) {
        int c = tid + j * 128;
        float val = g_agg[base + c] - as * cent[k * C_ + c];
        v[j] = val;
        s = fmaf(val, val, s);
    }
#pragma unroll
    for (int o = 16; o; o >>= 1) s += __shfl_xor_sync(0xFFFFFFFFu, s, o);
    if ((tid & 31) == 0) red[tid >> 5] = s;
    __syncthreads();
    if (tid == 0) bcast = red[0] + red[1] + red[2] + red[3];
    __syncthreads();
    float total = bcast;
    float invn = 1.f / fmaxf(sqrtf(total), EPSF);
#pragma unroll
    for (int j = 0; j < 4; j++) {
        int c = tid + j * 128;
        out[(size_t)n * KC * C_ + (size_t)k * C_ + c] = v[j] * invn;
    }
    if (tid == 0) atomicAdd(&g_nsq[n], total * invn * invn);
}

// ---------------- global L2 normalize ----------------
__global__ void __launch_bounds__(256) k_final(float* __restrict__ out) {
    int n = blockIdx.x;
    float scale = 1.f / fmaxf(sqrtf(g_nsq[n]), EPSF);
    size_t idx = (size_t)n * (KC * C_) + ((size_t)blockIdx.y * 256 + threadIdx.x) * 4;
    float4* o = reinterpret_cast<float4*>(out + idx);
    float4 v = *o;
    v.x *= scale; v.y *= scale; v.z *= scale; v.w *= scale;
    *o = v;
}

// ---------------- launch ----------------
extern "C" void kernel_launch(void* const* d_in, const int* in_sizes, int n_in,
                              void* d_out, int out_size) {
    const float* x    = (const float*)d_in[0];
    const float* w    = (const float*)d_in[1];
    const float* b    = (const float*)d_in[2];
    const float* cent = (const float*)d_in[3];
    float* out = (float*)d_out;

    k_gemm1<<<dim3(N_, 8), 128>>>(x, w, b);
    k_gemm2<<<dim3(N_, 8), 128>>>(x);
    k_rownorm<<<dim3(N_, KC), 128>>>(cent, out);
    k_final<<<dim3(N_, 32), 256>>>(out);
}